// round 13
// baseline (speedup 1.0000x reference)
#include <cuda_runtime.h>
#include <cuda_bf16.h>
#include <cuda_fp16.h>
#include <math.h>

#define NN 16384
#define EE 262144

// ---------------- scratch ----------------
__device__ float g_bufA[2 * NN * 128];
__device__ float g_bufB[2 * NN * 128];
__device__ __half g_sim[(size_t)NN * NN];    // 0.5 GiB sim scratch (fp16)
__device__ float g_af[2][NN * 32];
__device__ __half g_h16[2][NN * 32];         // fp16 copy of af for MMA
__device__ int   g_deg[2][NN];
__device__ float g_dinv[2][NN];
__device__ int   g_rowstart[2][NN + 1];
__device__ int   g_cursor[2][NN];
__device__ int   g_csrcol[2][EE];
__device__ unsigned g_umin_, g_umax_;
__device__ unsigned g_hist[16];
__device__ float g_colsum[2][32];
__device__ float g_tg[2][32];
__device__ float g_pool[2][32];
__device__ float g_scores[16];

__device__ __forceinline__ unsigned fmap(float f) {
    unsigned u = __float_as_uint(f);
    return u ^ ((((int)u) >> 31) | 0x80000000u);
}
__device__ __forceinline__ float funmap(unsigned u) {
    unsigned b = (u & 0x80000000u) ? (u ^ 0x80000000u) : ~u;
    return __uint_as_float(b);
}
__device__ __forceinline__ unsigned packh2(float a, float b) {
    __half2 t = __floats2half2_rn(a, b);
    return *reinterpret_cast<unsigned*>(&t);
}

// ---------------- init ----------------
__global__ void zero_kernel() {
    int i = blockIdx.x * 256 + threadIdx.x;      // grid 128 -> 32768
    ((int*)g_deg)[i] = 0;
    if (i < 16) g_hist[i] = 0;
    if (i < 64) { ((float*)g_colsum)[i] = 0.0f; ((float*)g_pool)[i] = 0.0f; }
    if (i == 0) { g_umin_ = 0xFFFFFFFFu; g_umax_ = 0u; }
}

// ---------------- degree (batched) ----------------
__global__ void deg_kernel(const int* __restrict__ e1, const int* __restrict__ e2) {
    int z = blockIdx.z;
    const int* rows = z ? e2 : e1;
    int e = blockIdx.x * 256 + threadIdx.x;
    atomicAdd(&g_deg[z][rows[e]], 1);
}

// ---------------- dinv + exclusive scan ----------------
__global__ void scan_kernel() {
    int g = blockIdx.x;
    __shared__ int part[512];
    int tid = threadIdx.x;
    int base = tid * 32;
    int d[32];
    int s = 0;
#pragma unroll
    for (int i = 0; i < 32; i++) {
        d[i] = g_deg[g][base + i];
        g_dinv[g][base + i] = rsqrtf((float)d[i] + 1.0f);
        s += d[i];
    }
    part[tid] = s;
    __syncthreads();
    for (int off = 1; off < 512; off <<= 1) {
        int v = (tid >= off) ? part[tid - off] : 0;
        __syncthreads();
        part[tid] += v;
        __syncthreads();
    }
    int run = part[tid] - s;
#pragma unroll
    for (int i = 0; i < 32; i++) {
        g_rowstart[g][base + i] = run;
        g_cursor[g][base + i] = run;
        run += d[i];
    }
    if (tid == 511) g_rowstart[g][NN] = run;
}

__global__ void scatter_kernel(const int* __restrict__ e1, const int* __restrict__ e2) {
    int z = blockIdx.z;
    const int* ei = z ? e2 : e1;
    int e = blockIdx.x * 256 + threadIdx.x;
    int p = atomicAdd(&g_cursor[z][ei[e]], 1);
    g_csrcol[z][p] = ei[EE + e];
}

// ---------------- dense GEMM (batched over z) ----------------
__global__ void __launch_bounds__(256) gemm_kernel(const float* __restrict__ A0,
                                                   const float* __restrict__ A1,
                                                   const float* __restrict__ W,
                                                   float* __restrict__ C,
                                                   int Nc, int K) {
    __shared__ float As[16][65];
    __shared__ float Bs[16][33];
    int z = blockIdx.z;
    const float* A = z ? A1 : A0;
    float* Cz = C + (size_t)z * NN * Nc;
    int tid = threadIdx.x;
    int bm = blockIdx.y * 64, bn = blockIdx.x * 32;
    int ty = tid >> 4, tx = tid & 15;
    float acc[4][2] = {};
    for (int k0 = 0; k0 < K; k0 += 16) {
#pragma unroll
        for (int l = 0; l < 4; l++) {
            int idx = l * 256 + tid;
            int m = idx >> 4, k = idx & 15;
            As[k][m] = A[(size_t)(bm + m) * K + k0 + k];
        }
#pragma unroll
        for (int l = 0; l < 2; l++) {
            int idx = l * 256 + tid;
            int k = idx >> 5, n = idx & 31;
            Bs[k][n] = W[(size_t)(k0 + k) * Nc + bn + n];
        }
        __syncthreads();
#pragma unroll
        for (int kk = 0; kk < 16; kk++) {
            float a[4], b[2];
#pragma unroll
            for (int i = 0; i < 4; i++) a[i] = As[kk][ty * 4 + i];
            b[0] = Bs[kk][tx * 2 + 0];
            b[1] = Bs[kk][tx * 2 + 1];
#pragma unroll
            for (int i = 0; i < 4; i++)
#pragma unroll
                for (int j = 0; j < 2; j++) acc[i][j] = fmaf(a[i], b[j], acc[i][j]);
        }
        __syncthreads();
    }
#pragma unroll
    for (int i = 0; i < 4; i++)
#pragma unroll
        for (int j = 0; j < 2; j++)
            Cz[(size_t)(bm + ty * 4 + i) * Nc + bn + tx * 2 + j] = acc[i][j];
}

// ---------------- CSR SpMM, fused bias+relu+self-loop; unrolled x4 for MLP ----------------
template <int C, int RELU, int SPLIT>
__global__ void __launch_bounds__(256) spmm_csr_kernel(const float* __restrict__ hbase,
                                                       const float* __restrict__ bias,
                                                       float* __restrict__ obase) {
    int z = blockIdx.z;
    const float* h = hbase + (size_t)z * NN * (C * 4);
    int gt = blockIdx.x * 256 + threadIdx.x;
    int row = gt / C;
    int c = gt % C;
    int s = g_rowstart[z][row], e = g_rowstart[z][row + 1];
    const float* dinv = g_dinv[z];
    const int* csr = g_csrcol[z];
    const float4* h4 = (const float4*)h;
    float4 acc = make_float4(0.f, 0.f, 0.f, 0.f);
    int j = s;
    int e4 = s + ((e - s) & ~3);
    for (; j < e4; j += 4) {
        int c0 = csr[j], c1 = csr[j + 1], c2 = csr[j + 2], c3 = csr[j + 3];
        float d0 = dinv[c0], d1 = dinv[c1], d2 = dinv[c2], d3 = dinv[c3];
        float4 v0 = h4[(size_t)c0 * C + c];
        float4 v1 = h4[(size_t)c1 * C + c];
        float4 v2 = h4[(size_t)c2 * C + c];
        float4 v3 = h4[(size_t)c3 * C + c];
        acc.x = fmaf(v0.x, d0, acc.x); acc.y = fmaf(v0.y, d0, acc.y);
        acc.z = fmaf(v0.z, d0, acc.z); acc.w = fmaf(v0.w, d0, acc.w);
        acc.x = fmaf(v1.x, d1, acc.x); acc.y = fmaf(v1.y, d1, acc.y);
        acc.z = fmaf(v1.z, d1, acc.z); acc.w = fmaf(v1.w, d1, acc.w);
        acc.x = fmaf(v2.x, d2, acc.x); acc.y = fmaf(v2.y, d2, acc.y);
        acc.z = fmaf(v2.z, d2, acc.z); acc.w = fmaf(v2.w, d2, acc.w);
        acc.x = fmaf(v3.x, d3, acc.x); acc.y = fmaf(v3.y, d3, acc.y);
        acc.z = fmaf(v3.z, d3, acc.z); acc.w = fmaf(v3.w, d3, acc.w);
    }
    for (; j < e; j++) {
        int col = csr[j];
        float d = dinv[col];
        float4 v = h4[(size_t)col * C + c];
        acc.x = fmaf(v.x, d, acc.x);
        acc.y = fmaf(v.y, d, acc.y);
        acc.z = fmaf(v.z, d, acc.z);
        acc.w = fmaf(v.w, d, acc.w);
    }
    float dr = dinv[row];
    float4 hv = h4[(size_t)row * C + c];
    float4 bv = ((const float4*)bias)[c];
    float dr2 = dr * dr;
    float4 o;
    o.x = acc.x * dr + hv.x * dr2 + bv.x;
    o.y = acc.y * dr + hv.y * dr2 + bv.y;
    o.z = acc.z * dr + hv.z * dr2 + bv.z;
    o.w = acc.w * dr + hv.w * dr2 + bv.w;
    if (RELU) {
        o.x = fmaxf(o.x, 0.f); o.y = fmaxf(o.y, 0.f);
        o.z = fmaxf(o.z, 0.f); o.w = fmaxf(o.w, 0.f);
    }
    if (SPLIT) {
        float* af = (float*)g_af[z];
        ((float4*)af)[(size_t)row * C + c] = o;
        ((uint2*)g_h16[z])[(size_t)row * C + c] =
            make_uint2(packh2(o.x, o.y), packh2(o.z, o.w));
    } else {
        float* out = obase + (size_t)z * NN * (C * 4);
        ((float4*)out)[(size_t)row * C + c] = o;
    }
}

// ================= sim GEMM: persistent fp16 mma.sync with pipelined tile loads =================
__device__ __forceinline__ void ldm4(unsigned& r0, unsigned& r1, unsigned& r2, unsigned& r3,
                                     unsigned addr) {
    asm volatile("ldmatrix.sync.aligned.m8n8.x4.shared.b16 {%0,%1,%2,%3}, [%4];"
                 : "=r"(r0), "=r"(r1), "=r"(r2), "=r"(r3) : "r"(addr));
}
__device__ __forceinline__ void mma16816h(float* c, const unsigned* a, unsigned b0, unsigned b1) {
    asm volatile("mma.sync.aligned.m16n8k16.row.col.f32.f16.f16.f32 "
                 "{%0,%1,%2,%3}, {%4,%5,%6,%7}, {%8,%9}, {%0,%1,%2,%3};"
                 : "+f"(c[0]), "+f"(c[1]), "+f"(c[2]), "+f"(c[3])
                 : "r"(a[0]), "r"(a[1]), "r"(a[2]), "r"(a[3]), "r"(b0), "r"(b1));
}

#define SIM_GRID 296

__global__ void __launch_bounds__(256, 2) sim_mma_kernel() {
    __shared__ alignas(16) char smem[20480];
    int tid = threadIdx.x;
    int lane = tid & 31, wid = tid >> 5;
    int wm = wid >> 1, wn = wid & 1;
    const int ntiles = (NN / 128) * (NN / 128);   // 16384
    int stride = gridDim.x;
    int idx = blockIdx.x;

    const uint4* A4 = (const uint4*)g_h16[0];
    const uint4* B4 = (const uint4*)g_h16[1];
    int r0 = tid >> 2, q0 = tid & 3;          // rows 0..63
    int r1 = r0 + 64;                          // rows 64..127

    uint4 pa0, pa1, pb0, pb1;
    if (idx < ntiles) {
        int rb = (idx >> 7) * 128, cb = (idx & 127) * 128;
        pa0 = A4[(size_t)(rb + r0) * 4 + q0];
        pa1 = A4[(size_t)(rb + r1) * 4 + q0];
        pb0 = B4[(size_t)(cb + r0) * 4 + q0];
        pb1 = B4[(size_t)(cb + r1) * 4 + q0];
    }

    unsigned sbase = (unsigned)__cvta_generic_to_shared(smem);
    int a_row_piece = (lane & 7) + ((lane >> 3) & 1) * 8;
    int a_colb = ((lane >> 4) & 1) * 16;
    int b_row_piece = (lane & 7) + ((lane >> 4) & 1) * 8;
    int b_colb = ((lane >> 3) & 1) * 16;

    float lmin = 3.4e38f, lmax = -3.4e38f;

    while (idx < ntiles) {
        __syncthreads();   // previous tile's smem reads complete
        *(uint4*)(smem + r0 * 80 + q0 * 16) = pa0;
        *(uint4*)(smem + r1 * 80 + q0 * 16) = pa1;
        *(uint4*)(smem + 10240 + r0 * 80 + q0 * 16) = pb0;
        *(uint4*)(smem + 10240 + r1 * 80 + q0 * 16) = pb1;
        __syncthreads();

        int rowbase = (idx >> 7) * 128;
        int colbase = (idx & 127) * 128;
        int nidx = idx + stride;
        if (nidx < ntiles) {   // issue next tile's loads before compute
            int rb = (nidx >> 7) * 128, cb = (nidx & 127) * 128;
            pa0 = A4[(size_t)(rb + r0) * 4 + q0];
            pa1 = A4[(size_t)(rb + r1) * 4 + q0];
            pb0 = B4[(size_t)(cb + r0) * 4 + q0];
            pb1 = B4[(size_t)(cb + r1) * 4 + q0];
        }

        float acc[2][8][4];
#pragma unroll
        for (int i = 0; i < 2; i++)
#pragma unroll
            for (int j = 0; j < 8; j++)
#pragma unroll
                for (int q = 0; q < 4; q++) acc[i][j][q] = 0.0f;

#pragma unroll
        for (int k = 0; k < 2; k++) {
            unsigned a[2][4], b[4][4];
#pragma unroll
            for (int mi = 0; mi < 2; mi++) {
                unsigned addr = sbase +
                                (unsigned)((wm * 32 + mi * 16 + a_row_piece) * 80 + k * 32 + a_colb);
                ldm4(a[mi][0], a[mi][1], a[mi][2], a[mi][3], addr);
            }
#pragma unroll
            for (int nj = 0; nj < 4; nj++) {
                unsigned addr = sbase + 10240u +
                                (unsigned)((wn * 64 + nj * 16 + b_row_piece) * 80 + k * 32 + b_colb);
                ldm4(b[nj][0], b[nj][1], b[nj][2], b[nj][3], addr);
            }
#pragma unroll
            for (int mi = 0; mi < 2; mi++)
#pragma unroll
                for (int n8 = 0; n8 < 8; n8++)
                    mma16816h(acc[mi][n8], a[mi], b[n8 >> 1][(n8 & 1) * 2],
                              b[n8 >> 1][(n8 & 1) * 2 + 1]);
        }

        int row0 = rowbase + wm * 32 + (lane >> 2);
        int colb = colbase + wn * 64 + (lane & 3) * 2;
#pragma unroll
        for (int mi = 0; mi < 2; mi++) {
#pragma unroll
            for (int n8 = 0; n8 < 8; n8++) {
                float v0 = acc[mi][n8][0], v1 = acc[mi][n8][1];
                float v2 = acc[mi][n8][2], v3 = acc[mi][n8][3];
                lmin = fminf(lmin, fminf(fminf(v0, v1), fminf(v2, v3)));
                lmax = fmaxf(lmax, fmaxf(fmaxf(v0, v1), fmaxf(v2, v3)));
                int r = row0 + mi * 16;
                int c = colb + n8 * 8;
                __stcs((unsigned*)&g_sim[(size_t)r * NN + c], packh2(v0, v1));
                __stcs((unsigned*)&g_sim[(size_t)(r + 8) * NN + c], packh2(v2, v3));
            }
        }
        idx = nidx;
    }

    // block-level min/max reduce (once per block)
#pragma unroll
    for (int o = 16; o; o >>= 1) {
        lmin = fminf(lmin, __shfl_xor_sync(0xFFFFFFFFu, lmin, o));
        lmax = fmaxf(lmax, __shfl_xor_sync(0xFFFFFFFFu, lmax, o));
    }
    __syncthreads();
    float* red = (float*)smem;
    if (lane == 0) { red[wid] = lmin; red[8 + wid] = lmax; }
    __syncthreads();
    if (tid == 0) {
        float m = red[0], M = red[8];
#pragma unroll
        for (int w = 1; w < 8; w++) { m = fminf(m, red[w]); M = fmaxf(M, red[8 + w]); }
        atomicMin(&g_umin_, fmap(m));
        atomicMax(&g_umax_, fmap(M));
    }
}

// ---------------- streaming histogram over g_sim (fp16, 8 values per uint4) ----------------
__global__ void __launch_bounds__(256) hist_kernel() {
    __shared__ unsigned cnt[16 * 256];   // stride 256: bank == lane, conflict-free
    int tid = threadIdx.x;
#pragma unroll
    for (int b = 0; b < 16; b++) cnt[b * 256 + tid] = 0;
    __syncthreads();
    float vmin = funmap(g_umin_);
    float vmax = funmap(g_umax_);
    float scale = 16.0f / (vmax - vmin);
    float offs = -vmin * scale;
    const uint4* s4 = (const uint4*)g_sim;
    int total = (int)(((size_t)NN * NN) / 8);   // 33,554,432 uint4
    int stride = gridDim.x * 256;
    for (int i = blockIdx.x * 256 + tid; i < total; i += stride) {
        uint4 u = __ldcs(&s4[i]);
#pragma unroll
        for (int w = 0; w < 4; w++) {
            unsigned uw = (&u.x)[w];
            __half2 h = *reinterpret_cast<__half2*>(&uw);
            float2 f = __half22float2(h);
            int b0 = min(15, max(0, (int)fmaf(f.x, scale, offs)));
            int b1 = min(15, max(0, (int)fmaf(f.y, scale, offs)));
            cnt[b0 * 256 + tid]++;
            cnt[b1 * 256 + tid]++;
        }
    }
    __syncthreads();
    if (tid < 16) {
        unsigned s = 0;
        for (int c = 0; c < 256; c++) s += cnt[tid * 256 + c];
        atomicAdd(&g_hist[tid], s);
    }
}

// ---------------- attention pooling (batched) ----------------
__global__ void colsum_kernel() {
    int z = blockIdx.y;
    const float* af = g_af[z];
    int tid = threadIdx.x;
    int c = tid & 31, rg = tid >> 5;
    int base = blockIdx.x * 256;
    float s = 0.0f;
#pragma unroll 8
    for (int t = 0; t < 32; t++) s += af[(size_t)(base + rg + t * 8) * 32 + c];
    __shared__ float red[256];
    red[tid] = s;
    __syncthreads();
    if (rg == 0) {
        float tot = 0.0f;
#pragma unroll
        for (int w = 0; w < 8; w++) tot += red[w * 32 + c];
        atomicAdd(&g_colsum[z][c], tot);
    }
}

__global__ void tg_kernel(const float* __restrict__ attW) {
    int tid = threadIdx.x;       // 64 threads
    int g = tid >> 5, j = tid & 31;
    float s = 0.0f;
    for (int i = 0; i < 32; i++) s += (g_colsum[g][i] * (1.0f / (float)NN)) * attW[i * 32 + j];
    g_tg[g][j] = tanhf(s);
}

__global__ void __launch_bounds__(256) pool_kernel() {
    int z = blockIdx.y;
    const float* af = g_af[z];
    __shared__ float tg[32];
    int tid = threadIdx.x;
    if (tid < 32) tg[tid] = g_tg[z][tid];
    __syncthreads();
    int r = blockIdx.x * 256 + tid;
    const float4* row = (const float4*)(af + (size_t)r * 32);
    float x[32];
    float dot = 0.0f;
#pragma unroll
    for (int q = 0; q < 8; q++) {
        float4 v = row[q];
        x[q * 4 + 0] = v.x; x[q * 4 + 1] = v.y; x[q * 4 + 2] = v.z; x[q * 4 + 3] = v.w;
        dot += v.x * tg[q * 4] + v.y * tg[q * 4 + 1] + v.z * tg[q * 4 + 2] + v.w * tg[q * 4 + 3];
    }
    float g = 1.0f / (1.0f + expf(-dot));
#pragma unroll
    for (int c = 0; c < 32; c++) {
        float v = x[c] * g;
#pragma unroll
        for (int o = 16; o; o >>= 1) v += __shfl_xor_sync(0xFFFFFFFFu, v, o);
        if ((tid & 31) == 0) atomicAdd(&g_pool[z][c], v);
    }
}

// ---------------- tensor network + head ----------------
__global__ void tnet_kernel(const float* __restrict__ tW, const float* __restrict__ tWb,
                            const float* __restrict__ tb) {
    __shared__ float p1[32], p2[32];
    int tid = threadIdx.x;
    if (tid < 32) { p1[tid] = g_pool[0][tid]; p2[tid] = g_pool[1][tid]; }
    __syncthreads();
    if (tid < 16) {
        float s = 0.0f;
        for (int i = 0; i < 32; i++) {
            float a = p1[i];
            for (int j = 0; j < 32; j++) s += a * p2[j] * tW[i * 512 + j * 16 + tid];
        }
        float blk = 0.0f;
        for (int j = 0; j < 32; j++)
            blk += tWb[tid * 64 + j] * p1[j] + tWb[tid * 64 + 32 + j] * p2[j];
        g_scores[tid] = fmaxf(s + blk + tb[tid], 0.0f);
    }
}

__global__ void final_kernel(const float* __restrict__ fcW, const float* __restrict__ fcb,
                             const float* __restrict__ scW, const float* __restrict__ scb,
                             float* __restrict__ out) {
    __shared__ float comb[32];
    __shared__ float fc[16];
    int tid = threadIdx.x;
    if (tid < 16) comb[tid] = g_scores[tid];
    else comb[tid] = (float)g_hist[tid - 16] * (1.0f / ((float)NN * (float)NN));
    __syncthreads();
    if (tid < 16) {
        float s = fcb[tid];
        for (int m = 0; m < 32; m++) s += comb[m] * fcW[tid * 32 + m];
        fc[tid] = fmaxf(s, 0.0f);
    }
    __syncthreads();
    if (tid == 0) {
        float z = scb[0];
        for (int b = 0; b < 16; b++) z += fc[b] * scW[b];
        out[0] = 1.0f / (1.0f + expf(-z));
    }
}

// ---------------- host orchestration ----------------
extern "C" void kernel_launch(void* const* d_in, const int* in_sizes, int n_in,
                              void* d_out, int out_size) {
    const float* f1   = (const float*)d_in[0];
    const float* f2   = (const float*)d_in[1];
    const int*   ei1  = (const int*)d_in[2];
    const int*   ei2  = (const int*)d_in[3];
    const float* W1   = (const float*)d_in[4];
    const float* b1   = (const float*)d_in[5];
    const float* W2   = (const float*)d_in[6];
    const float* b2   = (const float*)d_in[7];
    const float* W3   = (const float*)d_in[8];
    const float* b3   = (const float*)d_in[9];
    const float* attW = (const float*)d_in[10];
    const float* tW   = (const float*)d_in[11];
    const float* tWb  = (const float*)d_in[12];
    const float* tb   = (const float*)d_in[13];
    const float* fcW  = (const float*)d_in[14];
    const float* fcb  = (const float*)d_in[15];
    const float* scW  = (const float*)d_in[16];
    const float* scb  = (const float*)d_in[17];
    float* out = (float*)d_out;

    void *pA, *pB;
    cudaGetSymbolAddress(&pA, g_bufA);
    cudaGetSymbolAddress(&pB, g_bufB);
    float* bufA = (float*)pA;
    float* bufB = (float*)pB;

    zero_kernel<<<128, 256>>>();
    deg_kernel<<<dim3(EE / 256, 1, 2), 256>>>(ei1, ei2);
    scan_kernel<<<2, 512>>>();
    scatter_kernel<<<dim3(EE / 256, 1, 2), 256>>>(ei1, ei2);

    // layer 1: 144 -> 128, relu
    gemm_kernel<<<dim3(4, NN / 64, 2), 256>>>(f1, f2, W1, bufA, 128, 144);
    spmm_csr_kernel<32, 1, 0><<<dim3((NN * 32) / 256, 1, 2), 256>>>(bufA, b1, bufB);

    // layer 2: 128 -> 64, relu
    gemm_kernel<<<dim3(2, NN / 64, 2), 256>>>(bufB, bufB + (size_t)NN * 128, W2, bufA, 64, 128);
    spmm_csr_kernel<16, 1, 0><<<dim3((NN * 16) / 256, 1, 2), 256>>>(bufA, b2, bufB);

    // layer 3: 64 -> 32, no relu, writes fp32 af + fp16 copy
    gemm_kernel<<<dim3(1, NN / 64, 2), 256>>>(bufB, bufB + (size_t)NN * 64, W3, bufA, 32, 64);
    spmm_csr_kernel<8, 0, 1><<<dim3((NN * 8) / 256, 1, 2), 256>>>(bufA, b3, nullptr);

    // sim: persistent pipelined fp16 compute pass (store + min/max), then streaming histogram
    sim_mma_kernel<<<SIM_GRID, 256>>>();
    hist_kernel<<<1184, 256>>>();

    // attention pools (batched)
    colsum_kernel<<<dim3(64, 2), 256>>>();
    tg_kernel<<<1, 64>>>(attW);
    pool_kernel<<<dim3(64, 2), 256>>>();

    tnet_kernel<<<1, 64>>>(tW, tWb, tb);
    final_kernel<<<1, 32>>>(fcW, fcb, scW, scb, out);
}

// round 14
// speedup vs baseline: 1.2118x; 1.2118x over previous
#include <cuda_runtime.h>
#include <cuda_bf16.h>
#include <cuda_fp16.h>
#include <math.h>

#define NN 16384
#define EE 262144

// ---------------- scratch ----------------
__device__ float g_bufA[2 * NN * 128];
__device__ float g_bufB[2 * NN * 128];
__device__ __half g_sim[(size_t)NN * NN];    // 0.5 GiB sim scratch (fp16)
__device__ float g_af[2][NN * 32];
__device__ __half g_h16[2][NN * 32];         // fp16 copy of af for MMA
__device__ int   g_deg[2][NN];
__device__ float g_dinv[2][NN];
__device__ int   g_rowstart[2][NN + 1];
__device__ int   g_cursor[2][NN];
__device__ int   g_csrcol[2][EE];
__device__ unsigned g_umin_, g_umax_;
__device__ unsigned g_hist[16];
__device__ float g_colsum[2][32];
__device__ float g_tg[2][32];
__device__ float g_pool[2][32];
__device__ float g_scores[16];

__device__ __forceinline__ unsigned fmap(float f) {
    unsigned u = __float_as_uint(f);
    return u ^ ((((int)u) >> 31) | 0x80000000u);
}
__device__ __forceinline__ float funmap(unsigned u) {
    unsigned b = (u & 0x80000000u) ? (u ^ 0x80000000u) : ~u;
    return __uint_as_float(b);
}
__device__ __forceinline__ unsigned packh2(float a, float b) {
    __half2 t = __floats2half2_rn(a, b);
    return *reinterpret_cast<unsigned*>(&t);
}

// ---------------- init ----------------
__global__ void zero_kernel() {
    int i = blockIdx.x * 256 + threadIdx.x;      // grid 128 -> 32768
    ((int*)g_deg)[i] = 0;
    if (i < 16) g_hist[i] = 0;
    if (i < 64) { ((float*)g_colsum)[i] = 0.0f; ((float*)g_pool)[i] = 0.0f; }
    if (i == 0) { g_umin_ = 0xFFFFFFFFu; g_umax_ = 0u; }
}

// ---------------- degree (batched) ----------------
__global__ void deg_kernel(const int* __restrict__ e1, const int* __restrict__ e2) {
    int z = blockIdx.z;
    const int* rows = z ? e2 : e1;
    int e = blockIdx.x * 256 + threadIdx.x;
    atomicAdd(&g_deg[z][rows[e]], 1);
}

// ---------------- dinv + exclusive scan ----------------
__global__ void scan_kernel() {
    int g = blockIdx.x;
    __shared__ int part[512];
    int tid = threadIdx.x;
    int base = tid * 32;
    int d[32];
    int s = 0;
#pragma unroll
    for (int i = 0; i < 32; i++) {
        d[i] = g_deg[g][base + i];
        g_dinv[g][base + i] = rsqrtf((float)d[i] + 1.0f);
        s += d[i];
    }
    part[tid] = s;
    __syncthreads();
    for (int off = 1; off < 512; off <<= 1) {
        int v = (tid >= off) ? part[tid - off] : 0;
        __syncthreads();
        part[tid] += v;
        __syncthreads();
    }
    int run = part[tid] - s;
#pragma unroll
    for (int i = 0; i < 32; i++) {
        g_rowstart[g][base + i] = run;
        g_cursor[g][base + i] = run;
        run += d[i];
    }
    if (tid == 511) g_rowstart[g][NN] = run;
}

__global__ void scatter_kernel(const int* __restrict__ e1, const int* __restrict__ e2) {
    int z = blockIdx.z;
    const int* ei = z ? e2 : e1;
    int e = blockIdx.x * 256 + threadIdx.x;
    int p = atomicAdd(&g_cursor[z][ei[e]], 1);
    g_csrcol[z][p] = ei[EE + e];
}

// ---------------- dense GEMM (batched over z) ----------------
__global__ void __launch_bounds__(256) gemm_kernel(const float* __restrict__ A0,
                                                   const float* __restrict__ A1,
                                                   const float* __restrict__ W,
                                                   float* __restrict__ C,
                                                   int Nc, int K) {
    __shared__ float As[16][65];
    __shared__ float Bs[16][33];
    int z = blockIdx.z;
    const float* A = z ? A1 : A0;
    float* Cz = C + (size_t)z * NN * Nc;
    int tid = threadIdx.x;
    int bm = blockIdx.y * 64, bn = blockIdx.x * 32;
    int ty = tid >> 4, tx = tid & 15;
    float acc[4][2] = {};
    for (int k0 = 0; k0 < K; k0 += 16) {
#pragma unroll
        for (int l = 0; l < 4; l++) {
            int idx = l * 256 + tid;
            int m = idx >> 4, k = idx & 15;
            As[k][m] = A[(size_t)(bm + m) * K + k0 + k];
        }
#pragma unroll
        for (int l = 0; l < 2; l++) {
            int idx = l * 256 + tid;
            int k = idx >> 5, n = idx & 31;
            Bs[k][n] = W[(size_t)(k0 + k) * Nc + bn + n];
        }
        __syncthreads();
#pragma unroll
        for (int kk = 0; kk < 16; kk++) {
            float a[4], b[2];
#pragma unroll
            for (int i = 0; i < 4; i++) a[i] = As[kk][ty * 4 + i];
            b[0] = Bs[kk][tx * 2 + 0];
            b[1] = Bs[kk][tx * 2 + 1];
#pragma unroll
            for (int i = 0; i < 4; i++)
#pragma unroll
                for (int j = 0; j < 2; j++) acc[i][j] = fmaf(a[i], b[j], acc[i][j]);
        }
        __syncthreads();
    }
#pragma unroll
    for (int i = 0; i < 4; i++)
#pragma unroll
        for (int j = 0; j < 2; j++)
            Cz[(size_t)(bm + ty * 4 + i) * Nc + bn + tx * 2 + j] = acc[i][j];
}

// ---------------- CSR SpMM, fused bias+relu+self-loop; unrolled x4 for MLP ----------------
template <int C, int RELU, int SPLIT>
__global__ void __launch_bounds__(256) spmm_csr_kernel(const float* __restrict__ hbase,
                                                       const float* __restrict__ bias,
                                                       float* __restrict__ obase) {
    int z = blockIdx.z;
    const float* h = hbase + (size_t)z * NN * (C * 4);
    int gt = blockIdx.x * 256 + threadIdx.x;
    int row = gt / C;
    int c = gt % C;
    int s = g_rowstart[z][row], e = g_rowstart[z][row + 1];
    const float* dinv = g_dinv[z];
    const int* csr = g_csrcol[z];
    const float4* h4 = (const float4*)h;
    float4 acc = make_float4(0.f, 0.f, 0.f, 0.f);
    int j = s;
    int e4 = s + ((e - s) & ~3);
    for (; j < e4; j += 4) {
        int c0 = csr[j], c1 = csr[j + 1], c2 = csr[j + 2], c3 = csr[j + 3];
        float d0 = dinv[c0], d1 = dinv[c1], d2 = dinv[c2], d3 = dinv[c3];
        float4 v0 = h4[(size_t)c0 * C + c];
        float4 v1 = h4[(size_t)c1 * C + c];
        float4 v2 = h4[(size_t)c2 * C + c];
        float4 v3 = h4[(size_t)c3 * C + c];
        acc.x = fmaf(v0.x, d0, acc.x); acc.y = fmaf(v0.y, d0, acc.y);
        acc.z = fmaf(v0.z, d0, acc.z); acc.w = fmaf(v0.w, d0, acc.w);
        acc.x = fmaf(v1.x, d1, acc.x); acc.y = fmaf(v1.y, d1, acc.y);
        acc.z = fmaf(v1.z, d1, acc.z); acc.w = fmaf(v1.w, d1, acc.w);
        acc.x = fmaf(v2.x, d2, acc.x); acc.y = fmaf(v2.y, d2, acc.y);
        acc.z = fmaf(v2.z, d2, acc.z); acc.w = fmaf(v2.w, d2, acc.w);
        acc.x = fmaf(v3.x, d3, acc.x); acc.y = fmaf(v3.y, d3, acc.y);
        acc.z = fmaf(v3.z, d3, acc.z); acc.w = fmaf(v3.w, d3, acc.w);
    }
    for (; j < e; j++) {
        int col = csr[j];
        float d = dinv[col];
        float4 v = h4[(size_t)col * C + c];
        acc.x = fmaf(v.x, d, acc.x);
        acc.y = fmaf(v.y, d, acc.y);
        acc.z = fmaf(v.z, d, acc.z);
        acc.w = fmaf(v.w, d, acc.w);
    }
    float dr = dinv[row];
    float4 hv = h4[(size_t)row * C + c];
    float4 bv = ((const float4*)bias)[c];
    float dr2 = dr * dr;
    float4 o;
    o.x = acc.x * dr + hv.x * dr2 + bv.x;
    o.y = acc.y * dr + hv.y * dr2 + bv.y;
    o.z = acc.z * dr + hv.z * dr2 + bv.z;
    o.w = acc.w * dr + hv.w * dr2 + bv.w;
    if (RELU) {
        o.x = fmaxf(o.x, 0.f); o.y = fmaxf(o.y, 0.f);
        o.z = fmaxf(o.z, 0.f); o.w = fmaxf(o.w, 0.f);
    }
    if (SPLIT) {
        float* af = (float*)g_af[z];
        ((float4*)af)[(size_t)row * C + c] = o;
        ((uint2*)g_h16[z])[(size_t)row * C + c] =
            make_uint2(packh2(o.x, o.y), packh2(o.z, o.w));
    } else {
        float* out = obase + (size_t)z * NN * (C * 4);
        ((float4*)out)[(size_t)row * C + c] = o;
    }
}

// ================= sim GEMM via mma.sync fp16: smem-staged coalesced fp16 store =================
#define OFF_B 10240

__device__ __forceinline__ void ldm4(unsigned& r0, unsigned& r1, unsigned& r2, unsigned& r3,
                                     unsigned addr) {
    asm volatile("ldmatrix.sync.aligned.m8n8.x4.shared.b16 {%0,%1,%2,%3}, [%4];"
                 : "=r"(r0), "=r"(r1), "=r"(r2), "=r"(r3) : "r"(addr));
}
__device__ __forceinline__ void mma16816h(float* c, const unsigned* a, unsigned b0, unsigned b1) {
    asm volatile("mma.sync.aligned.m16n8k16.row.col.f32.f16.f16.f32 "
                 "{%0,%1,%2,%3}, {%4,%5,%6,%7}, {%8,%9}, {%0,%1,%2,%3};"
                 : "+f"(c[0]), "+f"(c[1]), "+f"(c[2]), "+f"(c[3])
                 : "r"(a[0]), "r"(a[1]), "r"(a[2]), "r"(a[3]), "r"(b0), "r"(b1));
}

__global__ void __launch_bounds__(256) sim_mma_kernel() {
    __shared__ alignas(16) char smem[20480];
    int tid = threadIdx.x;
    int lane = tid & 31, wid = tid >> 5;
    int wm = wid >> 1, wn = wid & 1;
    int rowbase = blockIdx.y * 128;
    int colbase = blockIdx.x * 128;

    const uint4* srcs[2] = {(const uint4*)g_h16[0], (const uint4*)g_h16[1]};
#pragma unroll
    for (int it = 0; it < 4; it++) {
        int buf = it >> 1;
        int rem = (it & 1) * 256 + tid;
        int r = rem >> 2, q = rem & 3;
        int tb = buf ? colbase : rowbase;
        uint4 v = srcs[buf][(size_t)(tb + r) * 4 + q];
        *(uint4*)(smem + buf * 10240 + r * 80 + q * 16) = v;
    }
    __syncthreads();

    float acc[2][8][4];
#pragma unroll
    for (int i = 0; i < 2; i++)
#pragma unroll
        for (int j = 0; j < 8; j++)
#pragma unroll
            for (int q = 0; q < 4; q++) acc[i][j][q] = 0.0f;

    unsigned sbase = (unsigned)__cvta_generic_to_shared(smem);
    int a_row_piece = (lane & 7) + ((lane >> 3) & 1) * 8;
    int a_colb = ((lane >> 4) & 1) * 16;
    int b_row_piece = (lane & 7) + ((lane >> 4) & 1) * 8;
    int b_colb = ((lane >> 3) & 1) * 16;

#pragma unroll
    for (int k = 0; k < 2; k++) {
        unsigned a[2][4], b[4][4];
#pragma unroll
        for (int mi = 0; mi < 2; mi++) {
            unsigned addr = sbase +
                            (unsigned)((wm * 32 + mi * 16 + a_row_piece) * 80 + k * 32 + a_colb);
            ldm4(a[mi][0], a[mi][1], a[mi][2], a[mi][3], addr);
        }
#pragma unroll
        for (int nj = 0; nj < 4; nj++) {
            unsigned addr = sbase + OFF_B +
                            (unsigned)((wn * 64 + nj * 16 + b_row_piece) * 80 + k * 32 + b_colb);
            ldm4(b[nj][0], b[nj][1], b[nj][2], b[nj][3], addr);
        }
#pragma unroll
        for (int mi = 0; mi < 2; mi++)
#pragma unroll
            for (int n8 = 0; n8 < 8; n8++)
                mma16816h(acc[mi][n8], a[mi], b[n8 >> 1][(n8 & 1) * 2],
                          b[n8 >> 1][(n8 & 1) * 2 + 1]);
    }

    // fp32 min/max over accumulators (exact)
    float lmin = 3.4e38f, lmax = -3.4e38f;
#pragma unroll
    for (int mi = 0; mi < 2; mi++)
#pragma unroll
        for (int n8 = 0; n8 < 8; n8++) {
            lmin = fminf(lmin, fminf(fminf(acc[mi][n8][0], acc[mi][n8][1]),
                                     fminf(acc[mi][n8][2], acc[mi][n8][3])));
            lmax = fmaxf(lmax, fmaxf(fmaxf(acc[mi][n8][0], acc[mi][n8][1]),
                                     fmaxf(acc[mi][n8][2], acc[mi][n8][3])));
        }

    // stage fp16 tile through smem (two 64-row chunks, row stride 272B = conflict-free),
    // then fully-coalesced STG.128 stores.
    int chunk_of_warp = wm >> 1;               // warps 0-3 own rows 0-63, warps 4-7 own 64-127
#pragma unroll
    for (int ch = 0; ch < 2; ch++) {
        __syncthreads();                       // tile smem (or previous chunk) free
        if (chunk_of_warp == ch) {
            int lr = (wm & 1) * 32 + (lane >> 2);
            int lcb = (wn * 64 + (lane & 3) * 2) * 2;   // byte offset in row
#pragma unroll
            for (int mi = 0; mi < 2; mi++)
#pragma unroll
                for (int n8 = 0; n8 < 8; n8++) {
                    int r = lr + mi * 16;
                    int cb = lcb + n8 * 16;
                    *(unsigned*)(smem + r * 272 + cb) =
                        packh2(acc[mi][n8][0], acc[mi][n8][1]);
                    *(unsigned*)(smem + (r + 8) * 272 + cb) =
                        packh2(acc[mi][n8][2], acc[mi][n8][3]);
                }
        }
        __syncthreads();
#pragma unroll
        for (int k = 0; k < 4; k++) {
            int p = (k * 256 + tid) * 16;      // byte position in 64x256B logical tile
            int row = p >> 8;
            int off = p & 255;
            uint4 v = *(uint4*)(smem + row * 272 + off);
            __stcs((uint4*)&g_sim[(size_t)(rowbase + ch * 64 + row) * NN + colbase + (off >> 1)], v);
        }
    }

    // block min/max reduce
#pragma unroll
    for (int o = 16; o; o >>= 1) {
        lmin = fminf(lmin, __shfl_xor_sync(0xFFFFFFFFu, lmin, o));
        lmax = fmaxf(lmax, __shfl_xor_sync(0xFFFFFFFFu, lmax, o));
    }
    __syncthreads();
    float* red = (float*)smem;
    if (lane == 0) { red[wid] = lmin; red[8 + wid] = lmax; }
    __syncthreads();
    if (tid == 0) {
        float m = red[0], M = red[8];
#pragma unroll
        for (int w = 1; w < 8; w++) { m = fminf(m, red[w]); M = fmaxf(M, red[8 + w]); }
        atomicMin(&g_umin_, fmap(m));
        atomicMax(&g_umax_, fmap(M));
    }
}

// ---------------- streaming histogram over g_sim (fp16, 8 values per uint4) ----------------
__global__ void __launch_bounds__(256) hist_kernel() {
    __shared__ unsigned cnt[16 * 256];   // stride 256: bank == lane, conflict-free
    int tid = threadIdx.x;
#pragma unroll
    for (int b = 0; b < 16; b++) cnt[b * 256 + tid] = 0;
    __syncthreads();
    float vmin = funmap(g_umin_);
    float vmax = funmap(g_umax_);
    float scale = 16.0f / (vmax - vmin);
    float offs = -vmin * scale;
    const uint4* s4 = (const uint4*)g_sim;
    int total = (int)(((size_t)NN * NN) / 8);   // 33,554,432 uint4
    int stride = gridDim.x * 256;
    for (int i = blockIdx.x * 256 + tid; i < total; i += stride) {
        uint4 u = __ldcs(&s4[i]);
#pragma unroll
        for (int w = 0; w < 4; w++) {
            unsigned uw = (&u.x)[w];
            __half2 h = *reinterpret_cast<__half2*>(&uw);
            float2 f = __half22float2(h);
            int b0 = min(15, max(0, (int)fmaf(f.x, scale, offs)));
            int b1 = min(15, max(0, (int)fmaf(f.y, scale, offs)));
            cnt[b0 * 256 + tid]++;
            cnt[b1 * 256 + tid]++;
        }
    }
    __syncthreads();
    if (tid < 16) {
        unsigned s = 0;
        for (int c = 0; c < 256; c++) s += cnt[tid * 256 + c];
        atomicAdd(&g_hist[tid], s);
    }
}

// ---------------- attention pooling (batched) ----------------
__global__ void colsum_kernel() {
    int z = blockIdx.y;
    const float* af = g_af[z];
    int tid = threadIdx.x;
    int c = tid & 31, rg = tid >> 5;
    int base = blockIdx.x * 256;
    float s = 0.0f;
#pragma unroll 8
    for (int t = 0; t < 32; t++) s += af[(size_t)(base + rg + t * 8) * 32 + c];
    __shared__ float red[256];
    red[tid] = s;
    __syncthreads();
    if (rg == 0) {
        float tot = 0.0f;
#pragma unroll
        for (int w = 0; w < 8; w++) tot += red[w * 32 + c];
        atomicAdd(&g_colsum[z][c], tot);
    }
}

__global__ void tg_kernel(const float* __restrict__ attW) {
    int tid = threadIdx.x;       // 64 threads
    int g = tid >> 5, j = tid & 31;
    float s = 0.0f;
    for (int i = 0; i < 32; i++) s += (g_colsum[g][i] * (1.0f / (float)NN)) * attW[i * 32 + j];
    g_tg[g][j] = tanhf(s);
}

__global__ void __launch_bounds__(256) pool_kernel() {
    int z = blockIdx.y;
    const float* af = g_af[z];
    __shared__ float tg[32];
    int tid = threadIdx.x;
    if (tid < 32) tg[tid] = g_tg[z][tid];
    __syncthreads();
    int r = blockIdx.x * 256 + tid;
    const float4* row = (const float4*)(af + (size_t)r * 32);
    float x[32];
    float dot = 0.0f;
#pragma unroll
    for (int q = 0; q < 8; q++) {
        float4 v = row[q];
        x[q * 4 + 0] = v.x; x[q * 4 + 1] = v.y; x[q * 4 + 2] = v.z; x[q * 4 + 3] = v.w;
        dot += v.x * tg[q * 4] + v.y * tg[q * 4 + 1] + v.z * tg[q * 4 + 2] + v.w * tg[q * 4 + 3];
    }
    float g = 1.0f / (1.0f + expf(-dot));
#pragma unroll
    for (int c = 0; c < 32; c++) {
        float v = x[c] * g;
#pragma unroll
        for (int o = 16; o; o >>= 1) v += __shfl_xor_sync(0xFFFFFFFFu, v, o);
        if ((tid & 31) == 0) atomicAdd(&g_pool[z][c], v);
    }
}

// ---------------- tensor network + head ----------------
__global__ void tnet_kernel(const float* __restrict__ tW, const float* __restrict__ tWb,
                            const float* __restrict__ tb) {
    __shared__ float p1[32], p2[32];
    int tid = threadIdx.x;
    if (tid < 32) { p1[tid] = g_pool[0][tid]; p2[tid] = g_pool[1][tid]; }
    __syncthreads();
    if (tid < 16) {
        float s = 0.0f;
        for (int i = 0; i < 32; i++) {
            float a = p1[i];
            for (int j = 0; j < 32; j++) s += a * p2[j] * tW[i * 512 + j * 16 + tid];
        }
        float blk = 0.0f;
        for (int j = 0; j < 32; j++)
            blk += tWb[tid * 64 + j] * p1[j] + tWb[tid * 64 + 32 + j] * p2[j];
        g_scores[tid] = fmaxf(s + blk + tb[tid], 0.0f);
    }
}

__global__ void final_kernel(const float* __restrict__ fcW, const float* __restrict__ fcb,
                             const float* __restrict__ scW, const float* __restrict__ scb,
                             float* __restrict__ out) {
    __shared__ float comb[32];
    __shared__ float fc[16];
    int tid = threadIdx.x;
    if (tid < 16) comb[tid] = g_scores[tid];
    else comb[tid] = (float)g_hist[tid - 16] * (1.0f / ((float)NN * (float)NN));
    __syncthreads();
    if (tid < 16) {
        float s = fcb[tid];
        for (int m = 0; m < 32; m++) s += comb[m] * fcW[tid * 32 + m];
        fc[tid] = fmaxf(s, 0.0f);
    }
    __syncthreads();
    if (tid == 0) {
        float z = scb[0];
        for (int b = 0; b < 16; b++) z += fc[b] * scW[b];
        out[0] = 1.0f / (1.0f + expf(-z));
    }
}

// ---------------- host orchestration ----------------
extern "C" void kernel_launch(void* const* d_in, const int* in_sizes, int n_in,
                              void* d_out, int out_size) {
    const float* f1   = (const float*)d_in[0];
    const float* f2   = (const float*)d_in[1];
    const int*   ei1  = (const int*)d_in[2];
    const int*   ei2  = (const int*)d_in[3];
    const float* W1   = (const float*)d_in[4];
    const float* b1   = (const float*)d_in[5];
    const float* W2   = (const float*)d_in[6];
    const float* b2   = (const float*)d_in[7];
    const float* W3   = (const float*)d_in[8];
    const float* b3   = (const float*)d_in[9];
    const float* attW = (const float*)d_in[10];
    const float* tW   = (const float*)d_in[11];
    const float* tWb  = (const float*)d_in[12];
    const float* tb   = (const float*)d_in[13];
    const float* fcW  = (const float*)d_in[14];
    const float* fcb  = (const float*)d_in[15];
    const float* scW  = (const float*)d_in[16];
    const float* scb  = (const float*)d_in[17];
    float* out = (float*)d_out;

    void *pA, *pB;
    cudaGetSymbolAddress(&pA, g_bufA);
    cudaGetSymbolAddress(&pB, g_bufB);
    float* bufA = (float*)pA;
    float* bufB = (float*)pB;

    zero_kernel<<<128, 256>>>();
    deg_kernel<<<dim3(EE / 256, 1, 2), 256>>>(ei1, ei2);
    scan_kernel<<<2, 512>>>();
    scatter_kernel<<<dim3(EE / 256, 1, 2), 256>>>(ei1, ei2);

    // layer 1: 144 -> 128, relu
    gemm_kernel<<<dim3(4, NN / 64, 2), 256>>>(f1, f2, W1, bufA, 128, 144);
    spmm_csr_kernel<32, 1, 0><<<dim3((NN * 32) / 256, 1, 2), 256>>>(bufA, b1, bufB);

    // layer 2: 128 -> 64, relu
    gemm_kernel<<<dim3(2, NN / 64, 2), 256>>>(bufB, bufB + (size_t)NN * 128, W2, bufA, 64, 128);
    spmm_csr_kernel<16, 1, 0><<<dim3((NN * 16) / 256, 1, 2), 256>>>(bufA, b2, bufB);

    // layer 3: 64 -> 32, no relu, writes fp32 af + fp16 copy
    gemm_kernel<<<dim3(1, NN / 64, 2), 256>>>(bufB, bufB + (size_t)NN * 64, W3, bufA, 32, 64);
    spmm_csr_kernel<8, 0, 1><<<dim3((NN * 8) / 256, 1, 2), 256>>>(bufA, b3, nullptr);

    // sim: fp16 compute pass (staged coalesced store + fp32 min/max), then streaming histogram
    sim_mma_kernel<<<dim3(NN / 128, NN / 128), 256>>>();
    hist_kernel<<<1184, 256>>>();

    // attention pools (batched)
    colsum_kernel<<<dim3(64, 2), 256>>>();
    tg_kernel<<<1, 64>>>(attW);
    pool_kernel<<<dim3(64, 2), 256>>>();

    tnet_kernel<<<1, 64>>>(tW, tWb, tb);
    final_kernel<<<1, 32>>>(fcW, fcb, scW, scb, out);
}